// round 5
// baseline (speedup 1.0000x reference)
#include <cuda_runtime.h>
#include <cuda_fp16.h>
#include <cstdint>
#include <math.h>

#define Nn  50000
#define Rr  8
#define Ee  200000
#define EDd 400000
#define TOT (Rr * Ee)
#define NK  (Nn * Rr)   // 400000 CSR keys (dst*8 + rel)

// ---------------- scratch (__device__ globals; no allocation) ----------------
__device__ __align__(16) __half g_M16[(size_t)Nn * 2560];  // Xagg [N, 8*Kpad] fp16
__device__ __align__(16) __half g_X16[(size_t)Nn * 320];   // activations fp16
__device__ __align__(16) __half g_H16[(size_t)Nn * 256];   // hidden fp16
__device__ __align__(16) __half g_Wh [256 * 2560];         // Wcat^T hi [dout][8*Kpad]
__device__ __align__(16) __half g_Wl [256 * 2560];         // Wcat^T lo
__device__ __align__(16) float g_h2[(size_t)Nn * 128];
__device__ __align__(16) float g_h3[(size_t)Nn * 128];
__device__ __align__(16) float g_Qt[(size_t)Nn * 8];
__device__ __align__(16) float g_Qb[(size_t)Nn * 8];
__device__ int   g_deg_src[Rr * Nn];
__device__ int   g_deg_key[NK];
__device__ int   g_row_ptr[NK + 1];
__device__ int   g_cursor [NK];
__device__ int   g_epack  [TOT];   // src node id (rel implicit in segment)
__device__ float g_ew     [TOT];   // per-edge norm weight
__device__ int   g_blksum [512];
__device__ float g_bsum   [768];
__device__ float g_Wp     [512 * 8];
__device__ __align__(16) float g_cvec[8];

// ---------------- helpers ----------------
__device__ __forceinline__ uint32_t smem_u32(const void* p) {
    uint32_t a;
    asm("{ .reg .u64 t; cvta.to.shared.u64 t, %1; cvt.u32.u64 %0, t; }" : "=r"(a) : "l"(p));
    return a;
}
#define SWZ(b) ((b) ^ (((b) >> 3) & 0x70))

__device__ __forceinline__ void ldmx4(uint32_t* r, uint32_t addr) {
    asm volatile("ldmatrix.sync.aligned.m8n8.x4.shared.b16 {%0,%1,%2,%3}, [%4];"
        : "=r"(r[0]), "=r"(r[1]), "=r"(r[2]), "=r"(r[3]) : "r"(addr));
}
__device__ __forceinline__ void mma16816(float* c, const uint32_t* a, const uint32_t* b) {
    asm volatile(
        "mma.sync.aligned.m16n8k16.row.col.f32.f16.f16.f32 "
        "{%0,%1,%2,%3}, {%4,%5,%6,%7}, {%8,%9}, {%0,%1,%2,%3};"
        : "+f"(c[0]), "+f"(c[1]), "+f"(c[2]), "+f"(c[3])
        : "r"(a[0]), "r"(a[1]), "r"(a[2]), "r"(a[3]), "r"(b[0]), "r"(b[1]));
}
__device__ __forceinline__ void cpa16(uint32_t d, const void* s) {
    asm volatile("cp.async.cg.shared.global [%0], [%1], 16;" :: "r"(d), "l"(s));
}

// ---------------- graph build (CSR keyed by dst*8 + rel) ----------------
__global__ void k_zero() {
    int i = blockIdx.x * blockDim.x + threadIdx.x;
    if (i < NK) { g_deg_src[i] = 0; g_deg_key[i] = 0; }
}
__global__ void k_count(const int* __restrict__ src, const int* __restrict__ dst) {
    int i = blockIdx.x * blockDim.x + threadIdx.x;
    if (i < TOT) {
        int r = i / Ee;
        atomicAdd(&g_deg_src[r * Nn + src[i]], 1);
        atomicAdd(&g_deg_key[dst[i] * 8 + r], 1);
    }
}
__global__ void k_scan1() {
    __shared__ int sh[256];
    int b = blockIdx.x, t = threadIdx.x;
    int base = b * 1024 + t * 4;
    int v[4];
#pragma unroll
    for (int j = 0; j < 4; j++) {
        int idx = base + j;
        v[j] = (idx < NK) ? g_deg_key[idx] : 0;
    }
    int tsum = v[0] + v[1] + v[2] + v[3];
    sh[t] = tsum;
    __syncthreads();
    for (int off = 1; off < 256; off <<= 1) {
        int x = (t >= off) ? sh[t - off] : 0;
        __syncthreads();
        sh[t] += x;
        __syncthreads();
    }
    int run = sh[t] - tsum;
#pragma unroll
    for (int j = 0; j < 4; j++) {
        int idx = base + j;
        if (idx < NK) g_row_ptr[idx] = run;
        run += v[j];
    }
    if (t == 255) g_blksum[b] = sh[255];
}
__global__ void k_scan2(int nb) {
    if (threadIdx.x == 0 && blockIdx.x == 0) {
        int acc = 0;
        for (int i = 0; i < nb; i++) { int s = g_blksum[i]; g_blksum[i] = acc; acc += s; }
    }
}
__global__ void k_scan3() {
    int i = blockIdx.x * blockDim.x + threadIdx.x;
    if (i < NK) {
        int v = g_row_ptr[i] + g_blksum[i / 1024];
        g_row_ptr[i] = v;
        g_cursor[i]  = v;
    }
    if (i == 0) g_row_ptr[NK] = TOT;
}
__global__ void k_fill(const int* __restrict__ src, const int* __restrict__ dst) {
    int i = blockIdx.x * blockDim.x + threadIdx.x;
    if (i < TOT) {
        int r = i / Ee;
        int s = src[i], d = dst[i];
        int key = d * 8 + r;
        int pos = atomicAdd(&g_cursor[key], 1);
        g_epack[pos] = s;
        g_ew[pos] = rsqrtf((float)g_deg_src[r * Nn + s]) *
                    rsqrtf((float)g_deg_key[key]);
    }
}
__global__ void k_bsum(const float* __restrict__ b2a, const float* __restrict__ b2b,
                       const float* __restrict__ b3a, const float* __restrict__ b3b) {
    int t = blockIdx.x * blockDim.x + threadIdx.x;
    if (t < 256)      { float s = 0; for (int r = 0; r < Rr; r++) s += b2a[r * 256 + t];        g_bsum[t] = s; }
    else if (t < 384) { int j = t - 256; float s = 0; for (int r = 0; r < Rr; r++) s += b2b[r * 128 + j]; g_bsum[t] = s; }
    else if (t < 640) { int j = t - 384; float s = 0; for (int r = 0; r < Rr; r++) s += b3a[r * 256 + j]; g_bsum[t] = s; }
    else if (t < 768) { int j = t - 640; float s = 0; for (int r = 0; r < Rr; r++) s += b3b[r * 128 + j]; g_bsum[t] = s; }
}

// ---------------- fp16 conversions ----------------
__global__ void k_split_x16(const float* __restrict__ X, int K, int Kpad,
                            __half* __restrict__ out, int n)
{
    long long i = (long long)blockIdx.x * blockDim.x + threadIdx.x;
    if (i >= (long long)n * Kpad) return;
    int row = (int)(i / Kpad), k = (int)(i % Kpad);
    float v = (k < K) ? X[(size_t)row * K + k] : 0.f;
    out[i] = __float2half(v);
}

// W [r][K][dout] fp32 -> Wcat^T hi/lo [dout][8*Kpad]: entry n*Kcat + r*Kpad + k
__global__ void k_split_w16(const float* __restrict__ W, int K, int Kpad, int dout,
                            __half* __restrict__ hi, __half* __restrict__ lo)
{
    int i = blockIdx.x * blockDim.x + threadIdx.x;
    if (i >= Rr * dout * Kpad) return;
    int k = i % Kpad;
    int n = (i / Kpad) % dout;
    int r = i / (Kpad * dout);
    float v = (k < K) ? W[((size_t)r * K + k) * dout + n] : 0.f;
    __half h = __float2half(v);
    size_t d = (size_t)n * (8 * Kpad) + r * Kpad + k;
    hi[d] = h;
    lo[d] = __float2half(v - __half2float(h));
}

// ---------------- aggregation FIRST: Xagg[key][t] = sum_e w_e * X[src_e][t] ----------------
// block = key (dst*8+rel), threads = Kpad. X is L2-resident (25-32 MB).
__global__ void k_aggX(const __half* __restrict__ X, int Kpad, __half* __restrict__ out)
{
    int b = blockIdx.x;
    int t = threadIdx.x;
    int p0 = g_row_ptr[b], p1 = g_row_ptr[b + 1];
    float a0 = 0.f, a1 = 0.f;
    int p = p0;
    for (; p + 1 < p1; p += 2) {
        int   s0 = g_epack[p],     s1 = g_epack[p + 1];
        float w0 = g_ew[p],        w1 = g_ew[p + 1];
        a0 = fmaf(w0, __half2float(__ldg(&X[(size_t)s0 * Kpad + t])), a0);
        a1 = fmaf(w1, __half2float(__ldg(&X[(size_t)s1 * Kpad + t])), a1);
    }
    if (p < p1)
        a0 = fmaf(g_ew[p], __half2float(__ldg(&X[(size_t)g_epack[p] * Kpad + t])), a0);
    out[(size_t)b * Kpad + t] = __float2half(a0 + a1);
}

// ---------------- HMMA fp16 2-term GEMM with fused epilogue ----------------
// C[m, n] = A[m, 0:Kcat] . (Wh[n,:] + Wl[n,:]) + bias[n]   (mode0: relu->fp16, mode1: fp32)
// BM=128, BN=128, BK=64. 256 threads = 8 warps (4M x 2N), warp tile 32x64.
__global__ void __launch_bounds__(256, 2) k_gemm(
    const __half* __restrict__ A, int Kcat,
    const __half* __restrict__ Bh, const __half* __restrict__ Bl, int dout,
    const float* __restrict__ bias,
    __half* __restrict__ outH, float* __restrict__ outF, int mode)
{
    __shared__ __half sA [128 * 64];
    __shared__ __half sBh[128 * 64];
    __shared__ __half sBl[128 * 64];
    uint32_t uA = smem_u32(sA), uBH = smem_u32(sBh), uBL = smem_u32(sBl);

    int tid = threadIdx.x;
    int warp = tid >> 5, lane = tid & 31;
    int wm = warp & 3, wn = warp >> 2;
    int n0 = blockIdx.x * 128;
    int m0 = blockIdx.y * 128;

    float acc[2][8][4];
#pragma unroll
    for (int i = 0; i < 2; i++)
#pragma unroll
        for (int j = 0; j < 8; j++)
#pragma unroll
            for (int q = 0; q < 4; q++) acc[i][j][q] = 0.f;

    int a_row = (lane & 15);
    int a_cb  = (lane >> 4) << 4;
    int b_row = (lane & 7) + ((lane >> 4) << 3);
    int b_cb  = ((lane >> 3) & 1) << 4;

    int nch = Kcat >> 6;
    for (int c = 0; c < nch; c++) {
        int acol = c << 6;
#pragma unroll
        for (int it = 0; it < 4; it++) {
            int idx = it * 256 + tid;
            int row = idx >> 3, j = idx & 7;
            int gm = m0 + row; if (gm >= Nn) gm = Nn - 1;
            uint32_t o = SWZ((uint32_t)(row * 128 + j * 16));
            cpa16(uA + o,  A  + (size_t)gm * Kcat + acol + j * 8);
            cpa16(uBH + o, Bh + (size_t)(n0 + row) * Kcat + acol + j * 8);
            cpa16(uBL + o, Bl + (size_t)(n0 + row) * Kcat + acol + j * 8);
        }
        asm volatile("cp.async.commit_group;" ::: "memory");
        asm volatile("cp.async.wait_group 0;" ::: "memory");
        __syncthreads();

#pragma unroll
        for (int ks = 0; ks < 4; ks++) {
            uint32_t ah[2][4];
#pragma unroll
            for (int mt = 0; mt < 2; mt++) {
                uint32_t off = SWZ((uint32_t)((wm * 32 + mt * 16 + a_row) * 128 + ks * 32 + a_cb));
                ldmx4(ah[mt], uA + off);
            }
#pragma unroll
            for (int np = 0; np < 4; np++) {
                uint32_t th[4], tl[4];
                uint32_t off = SWZ((uint32_t)((wn * 64 + np * 16 + b_row) * 128 + ks * 32 + b_cb));
                ldmx4(th, uBH + off);
                ldmx4(tl, uBL + off);
#pragma unroll
                for (int mt = 0; mt < 2; mt++) {
                    mma16816(acc[mt][np * 2],     ah[mt], &th[0]);
                    mma16816(acc[mt][np * 2],     ah[mt], &tl[0]);
                    mma16816(acc[mt][np * 2 + 1], ah[mt], &th[2]);
                    mma16816(acc[mt][np * 2 + 1], ah[mt], &tl[2]);
                }
            }
        }
        __syncthreads();
    }

    // fused epilogue: +bias, (relu), write fp16 or fp32
    int erow = lane >> 2, ecol = (lane & 3) * 2;
#pragma unroll
    for (int mt = 0; mt < 2; mt++) {
        int gm0 = m0 + wm * 32 + mt * 16 + erow;
#pragma unroll
        for (int nt = 0; nt < 8; nt++) {
            int col = n0 + wn * 64 + nt * 8 + ecol;
            float b0 = bias[col], b1 = bias[col + 1];
            float v00 = acc[mt][nt][0] + b0, v01 = acc[mt][nt][1] + b1;
            float v10 = acc[mt][nt][2] + b0, v11 = acc[mt][nt][3] + b1;
            if (mode == 0) {
                v00 = fmaxf(v00, 0.f); v01 = fmaxf(v01, 0.f);
                v10 = fmaxf(v10, 0.f); v11 = fmaxf(v11, 0.f);
                if (gm0 < Nn)
                    *(__half2*)(outH + (size_t)gm0 * dout + col) = __floats2half2_rn(v00, v01);
                if (gm0 + 8 < Nn)
                    *(__half2*)(outH + (size_t)(gm0 + 8) * dout + col) = __floats2half2_rn(v10, v11);
            } else {
                if (gm0 < Nn)
                    *(float2*)(outF + (size_t)gm0 * dout + col) = make_float2(v00, v01);
                if (gm0 + 8 < Nn)
                    *(float2*)(outF + (size_t)(gm0 + 8) * dout + col) = make_float2(v10, v11);
            }
        }
    }
}

// ---------------- decoder ----------------
__global__ void k_wp(const float* __restrict__ Wp1, const float* __restrict__ bp1,
                     const float* __restrict__ Wp2, const float* __restrict__ bp2)
{
    int idx = blockIdx.x * blockDim.x + threadIdx.x;
    if (idx >= 513 * 8) return;
    int i = idx >> 3, c = idx & 7;
    if (i < 512) {
        float s = 0.f;
        for (int j = 0; j < 256; j++) s = fmaf(Wp1[i * 256 + j], Wp2[j * 8 + c], s);
        g_Wp[i * 8 + c] = s;
    } else {
        float s = bp2[c];
        for (int j = 0; j < 256; j++) s = fmaf(bp1[j], Wp2[j * 8 + c], s);
        g_cvec[c] = s;
    }
}

__global__ void k_q() {
    __shared__ float sWp[512 * 8];
    for (int i = threadIdx.x; i < 512 * 8; i += blockDim.x) sWp[i] = g_Wp[i];
    __syncthreads();
    int n = blockIdx.x * blockDim.x + threadIdx.x;
    if (n >= Nn) return;
    float qt[8], qb[8];
#pragma unroll
    for (int c = 0; c < 8; c++) { qt[c] = 0.f; qb[c] = 0.f; }
    const float* h2 = &g_h2[(size_t)n * 128];
    const float* h3 = &g_h3[(size_t)n * 128];
    for (int j = 0; j < 128; j++) {
        float x2 = h2[j], x3 = h3[j];
#pragma unroll
        for (int c = 0; c < 8; c++) {
            qt[c] = fmaf(x2, sWp[j * 8 + c],         qt[c]);
            qt[c] = fmaf(x3, sWp[(128 + j) * 8 + c], qt[c]);
            qb[c] = fmaf(x2, sWp[(256 + j) * 8 + c], qb[c]);
            qb[c] = fmaf(x3, sWp[(384 + j) * 8 + c], qb[c]);
        }
    }
#pragma unroll
    for (int c = 0; c < 8; c++) {
        g_Qt[(size_t)n * 8 + c] = qt[c];
        g_Qb[(size_t)n * 8 + c] = qb[c];
    }
}

__global__ void k_edge(const int* __restrict__ ds, const int* __restrict__ dd,
                       float* __restrict__ out)
{
    int e = blockIdx.x * blockDim.x + threadIdx.x;
    if (e >= EDd) return;
    int s = ds[e], d = dd[e];
    const float4* qt = (const float4*)&g_Qt[(size_t)s * 8];
    const float4* qb = (const float4*)&g_Qb[(size_t)d * 8];
    const float4* cv = (const float4*)g_cvec;
    float4 t0 = qt[0], t1 = qt[1], b0 = qb[0], b1 = qb[1], c0 = cv[0], c1 = cv[1];
    float4 o0 = make_float4(t0.x + b0.x + c0.x, t0.y + b0.y + c0.y,
                            t0.z + b0.z + c0.z, t0.w + b0.w + c0.w);
    float4 o1 = make_float4(t1.x + b1.x + c1.x, t1.y + b1.y + c1.y,
                            t1.z + b1.z + c1.z, t1.w + b1.w + c1.w);
    float4* o = (float4*)out;
    o[2 * e]     = o0;
    o[2 * e + 1] = o1;
}

// ---------------- launcher ----------------
extern "C" void kernel_launch(void* const* d_in, const int* in_sizes, int n_in,
                              void* d_out, int out_size)
{
    const float* x2  = (const float*)d_in[0];
    const float* x3  = (const float*)d_in[1];
    const int*   src = (const int*)d_in[2];
    const int*   dst = (const int*)d_in[3];
    const int*   dsr = (const int*)d_in[4];
    const int*   dds = (const int*)d_in[5];
    const float* W2a = (const float*)d_in[6];
    const float* b2a = (const float*)d_in[7];
    const float* W2b = (const float*)d_in[8];
    const float* b2b = (const float*)d_in[9];
    const float* W3a = (const float*)d_in[10];
    const float* b3a = (const float*)d_in[11];
    const float* W3b = (const float*)d_in[12];
    const float* b3b = (const float*)d_in[13];
    const float* Wp1 = (const float*)d_in[14];
    const float* bp1 = (const float*)d_in[15];
    const float* Wp2 = (const float*)d_in[16];
    const float* bp2 = (const float*)d_in[17];
    float* out = (float*)d_out;

    void *pM, *pX, *pH, *pWh, *pWl, *ph2, *ph3, *pBsum;
    cudaGetSymbolAddress(&pM, g_M16);
    cudaGetSymbolAddress(&pX, g_X16);
    cudaGetSymbolAddress(&pH, g_H16);
    cudaGetSymbolAddress(&pWh, g_Wh);
    cudaGetSymbolAddress(&pWl, g_Wl);
    cudaGetSymbolAddress(&ph2, g_h2);
    cudaGetSymbolAddress(&ph3, g_h3);
    cudaGetSymbolAddress(&pBsum, g_bsum);
    __half* M  = (__half*)pM;
    __half* X  = (__half*)pX;
    __half* H  = (__half*)pH;
    __half* Wh = (__half*)pWh;
    __half* Wl = (__half*)pWl;
    float*  h2 = (float*)ph2;
    float*  h3 = (float*)ph3;
    float*  bsum = (float*)pBsum;

    // ---- graph build (CSR keyed by dst*8+rel, shared by all 4 aggregations) ----
    k_zero <<<(NK + 255) / 256, 256>>>();
    k_count<<<(TOT + 255) / 256, 256>>>(src, dst);
    k_scan1<<<(NK + 1023) / 1024, 256>>>();
    k_scan2<<<1, 32>>>((NK + 1023) / 1024);
    k_scan3<<<(NK + 255) / 256, 256>>>();
    k_fill <<<(TOT + 255) / 256, 256>>>(src, dst);
    k_bsum <<<3, 256>>>(b2a, b2b, b3a, b3b);

    dim3 gemmA(2, (Nn + 127) / 128);   // dout=256
    dim3 gemmB(1, (Nn + 127) / 128);   // dout=128

    // ---- tower 2 (K=256) ----
    k_split_x16<<<((long long)Nn * 256 + 255) / 256, 256>>>(x2, 256, 256, X, Nn);
    k_split_w16<<<(Rr * 256 * 256 + 255) / 256, 256>>>(W2a, 256, 256, 256, Wh, Wl);
    k_aggX<<<NK, 256>>>(X, 256, M);
    k_gemm<<<gemmA, 256>>>(M, 2048, Wh, Wl, 256, bsum + 0, H, (float*)0, 0);
    k_split_w16<<<(Rr * 128 * 256 + 255) / 256, 256>>>(W2b, 256, 256, 128, Wh, Wl);
    k_aggX<<<NK, 256>>>(H, 256, M);
    k_gemm<<<gemmB, 256>>>(M, 2048, Wh, Wl, 128, bsum + 256, (__half*)0, h2, 1);

    // ---- tower 3 (K=300 -> pad 320) ----
    k_split_x16<<<((long long)Nn * 320 + 255) / 256, 256>>>(x3, 300, 320, X, Nn);
    k_split_w16<<<(Rr * 256 * 320 + 255) / 256, 256>>>(W3a, 300, 320, 256, Wh, Wl);
    k_aggX<<<NK, 320>>>(X, 320, M);
    k_gemm<<<gemmA, 256>>>(M, 2560, Wh, Wl, 256, bsum + 384, H, (float*)0, 0);
    k_split_w16<<<(Rr * 128 * 256 + 255) / 256, 256>>>(W3b, 256, 256, 128, Wh, Wl);
    k_aggX<<<NK, 256>>>(H, 256, M);
    k_gemm<<<gemmB, 256>>>(M, 2048, Wh, Wl, 128, bsum + 640, (__half*)0, h3, 1);

    // ---- decoder ----
    k_wp<<<(513 * 8 + 127) / 128, 128>>>(Wp1, bp1, Wp2, bp2);
    k_q<<<(Nn + 255) / 256, 256>>>();
    k_edge<<<(EDd + 255) / 256, 256>>>(dsr, dds, out);
}

// round 6
// speedup vs baseline: 1.0478x; 1.0478x over previous
#include <cuda_runtime.h>
#include <cuda_fp16.h>
#include <cstdint>
#include <math.h>

#define Nn  50000
#define Rr  8
#define Ee  200000
#define EDd 400000
#define TOT (Rr * Ee)
#define NK  (Nn * Rr)   // 400000 CSR keys (dst*8 + rel)

// ---------------- scratch (__device__ globals; no allocation) ----------------
__device__ __align__(16) __half g_M16[(size_t)Nn * 2560];  // Xagg [node][8*Kpad] fp16
__device__ __align__(16) __half g_X16[(size_t)Nn * 320];   // activations fp16
__device__ __align__(16) __half g_H16[(size_t)Nn * 256];   // hidden fp16
__device__ __align__(16) __half g_Wh [256 * 2560];         // Wcat^T hi [dout][8*Kpad]
__device__ __align__(16) __half g_Wl [256 * 2560];         // Wcat^T lo
__device__ __align__(16) float g_h2[(size_t)Nn * 128];
__device__ __align__(16) float g_h3[(size_t)Nn * 128];
__device__ __align__(16) float g_Qt[(size_t)Nn * 8];
__device__ __align__(16) float g_Qb[(size_t)Nn * 8];
__device__ int   g_deg_src[Rr * Nn];
__device__ int   g_deg_key[NK];
__device__ int   g_row_ptr[NK + 1];
__device__ int   g_cursor [NK];
__device__ int   g_epack  [TOT];   // src node id (rel implicit in segment)
__device__ float g_ew     [TOT];   // per-edge norm weight
__device__ int   g_blksum [512];
__device__ float g_bsum   [768];
__device__ float g_Wp     [512 * 8];
__device__ __align__(16) float g_cvec[8];

// ---------------- helpers ----------------
__device__ __forceinline__ uint32_t smem_u32(const void* p) {
    uint32_t a;
    asm("{ .reg .u64 t; cvta.to.shared.u64 t, %1; cvt.u32.u64 %0, t; }" : "=r"(a) : "l"(p));
    return a;
}
#define SWZ(b) ((b) ^ (((b) >> 3) & 0x70))

__device__ __forceinline__ void ldmx4(uint32_t* r, uint32_t addr) {
    asm volatile("ldmatrix.sync.aligned.m8n8.x4.shared.b16 {%0,%1,%2,%3}, [%4];"
        : "=r"(r[0]), "=r"(r[1]), "=r"(r[2]), "=r"(r[3]) : "r"(addr));
}
__device__ __forceinline__ void mma16816(float* c, const uint32_t* a, const uint32_t* b) {
    asm volatile(
        "mma.sync.aligned.m16n8k16.row.col.f32.f16.f16.f32 "
        "{%0,%1,%2,%3}, {%4,%5,%6,%7}, {%8,%9}, {%0,%1,%2,%3};"
        : "+f"(c[0]), "+f"(c[1]), "+f"(c[2]), "+f"(c[3])
        : "r"(a[0]), "r"(a[1]), "r"(a[2]), "r"(a[3]), "r"(b[0]), "r"(b[1]));
}
__device__ __forceinline__ void cpa16(uint32_t d, const void* s) {
    asm volatile("cp.async.cg.shared.global [%0], [%1], 16;" :: "r"(d), "l"(s));
}
#define CP_COMMIT() asm volatile("cp.async.commit_group;" ::: "memory")

// ---------------- graph build (CSR keyed by dst*8 + rel) ----------------
__global__ void k_zero() {
    int i = blockIdx.x * blockDim.x + threadIdx.x;
    if (i < NK) { g_deg_src[i] = 0; g_deg_key[i] = 0; }
}
__global__ void k_count(const int* __restrict__ src, const int* __restrict__ dst) {
    int i = blockIdx.x * blockDim.x + threadIdx.x;
    if (i < TOT) {
        int r = i / Ee;
        atomicAdd(&g_deg_src[r * Nn + src[i]], 1);
        atomicAdd(&g_deg_key[dst[i] * 8 + r], 1);
    }
}
__global__ void k_scan1() {
    __shared__ int sh[256];
    int b = blockIdx.x, t = threadIdx.x;
    int base = b * 1024 + t * 4;
    int v[4];
#pragma unroll
    for (int j = 0; j < 4; j++) {
        int idx = base + j;
        v[j] = (idx < NK) ? g_deg_key[idx] : 0;
    }
    int tsum = v[0] + v[1] + v[2] + v[3];
    sh[t] = tsum;
    __syncthreads();
    for (int off = 1; off < 256; off <<= 1) {
        int x = (t >= off) ? sh[t - off] : 0;
        __syncthreads();
        sh[t] += x;
        __syncthreads();
    }
    int run = sh[t] - tsum;
#pragma unroll
    for (int j = 0; j < 4; j++) {
        int idx = base + j;
        if (idx < NK) g_row_ptr[idx] = run;
        run += v[j];
    }
    if (t == 255) g_blksum[b] = sh[255];
}
__global__ void k_scan2(int nb) {
    if (threadIdx.x == 0 && blockIdx.x == 0) {
        int acc = 0;
        for (int i = 0; i < nb; i++) { int s = g_blksum[i]; g_blksum[i] = acc; acc += s; }
    }
}
__global__ void k_scan3() {
    int i = blockIdx.x * blockDim.x + threadIdx.x;
    if (i < NK) {
        int v = g_row_ptr[i] + g_blksum[i / 1024];
        g_row_ptr[i] = v;
        g_cursor[i]  = v;
    }
    if (i == 0) g_row_ptr[NK] = TOT;
}
__global__ void k_fill(const int* __restrict__ src, const int* __restrict__ dst) {
    int i = blockIdx.x * blockDim.x + threadIdx.x;
    if (i < TOT) {
        int r = i / Ee;
        int s = src[i], d = dst[i];
        int key = d * 8 + r;
        int pos = atomicAdd(&g_cursor[key], 1);
        g_epack[pos] = s;
        g_ew[pos] = rsqrtf((float)g_deg_src[r * Nn + s]) *
                    rsqrtf((float)g_deg_key[key]);
    }
}
__global__ void k_bsum(const float* __restrict__ b2a, const float* __restrict__ b2b,
                       const float* __restrict__ b3a, const float* __restrict__ b3b) {
    int t = blockIdx.x * blockDim.x + threadIdx.x;
    if (t < 256)      { float s = 0; for (int r = 0; r < Rr; r++) s += b2a[r * 256 + t];        g_bsum[t] = s; }
    else if (t < 384) { int j = t - 256; float s = 0; for (int r = 0; r < Rr; r++) s += b2b[r * 128 + j]; g_bsum[t] = s; }
    else if (t < 640) { int j = t - 384; float s = 0; for (int r = 0; r < Rr; r++) s += b3a[r * 256 + j]; g_bsum[t] = s; }
    else if (t < 768) { int j = t - 640; float s = 0; for (int r = 0; r < Rr; r++) s += b3b[r * 128 + j]; g_bsum[t] = s; }
}

// ---------------- fp16 conversions ----------------
__global__ void k_split_x16(const float* __restrict__ X, int K, int Kpad,
                            __half* __restrict__ out, int n)
{
    long long i = (long long)blockIdx.x * blockDim.x + threadIdx.x;
    if (i >= (long long)n * Kpad) return;
    int row = (int)(i / Kpad), k = (int)(i % Kpad);
    float v = (k < K) ? X[(size_t)row * K + k] : 0.f;
    out[i] = __float2half(v);
}

// W [r][K][dout] fp32 -> Wcat^T hi/lo [dout][8*Kpad]: entry n*(8*Kpad) + r*Kpad + k
__global__ void k_split_w16(const float* __restrict__ W, int K, int Kpad, int dout,
                            __half* __restrict__ hi, __half* __restrict__ lo)
{
    int i = blockIdx.x * blockDim.x + threadIdx.x;
    if (i >= Rr * dout * Kpad) return;
    int k = i % Kpad;
    int n = (i / Kpad) % dout;
    int r = i / (Kpad * dout);
    float v = (k < K) ? W[((size_t)r * K + k) * dout + n] : 0.f;
    __half h = __float2half(v);
    size_t d = (size_t)n * (8 * Kpad) + r * Kpad + k;
    hi[d] = h;
    lo[d] = __float2half(v - __half2float(h));
}

// ---------------- aggregation FIRST: Xagg[key][t] = sum_e w_e * X[src_e][t] ----------------
// block = key (dst*8+rel), threads = Kpad. X is L2-resident (25-32 MB).
__global__ void k_aggX(const __half* __restrict__ X, int Kpad, __half* __restrict__ out)
{
    int b = blockIdx.x;
    int t = threadIdx.x;
    int p0 = g_row_ptr[b], p1 = g_row_ptr[b + 1];
    float a0 = 0.f, a1 = 0.f;
    int p = p0;
    for (; p + 1 < p1; p += 2) {
        int   s0 = g_epack[p],     s1 = g_epack[p + 1];
        float w0 = g_ew[p],        w1 = g_ew[p + 1];
        a0 = fmaf(w0, __half2float(__ldg(&X[(size_t)s0 * Kpad + t])), a0);
        a1 = fmaf(w1, __half2float(__ldg(&X[(size_t)s1 * Kpad + t])), a1);
    }
    if (p < p1)
        a0 = fmaf(g_ew[p], __half2float(__ldg(&X[(size_t)g_epack[p] * Kpad + t])), a0);
    out[(size_t)b * Kpad + t] = __float2half(a0 + a1);
}

// ---------------- pipelined HMMA fp16 2-term GEMM with fused epilogue ----------------
// C[m, n] = Xagg[m, 0:Kcat] . (Wh[n,:] + Wl[n,:]) + bias[n]  (mode0: relu->fp16, mode1: fp32)
// BM=128, BN=64, BK=64. 256 threads = 8 warps (4M x 2N), warp tile 32x32.
// cp.async double-buffered (2 stages x 32KB).
#define OFF_A  0
#define OFF_BH 16384
#define OFF_BL 24576
#define STAGE  32768

__global__ void __launch_bounds__(256, 2) k_gemm(
    const __half* __restrict__ A, int Kcat,
    const __half* __restrict__ Bh, const __half* __restrict__ Bl, int dout,
    const float* __restrict__ bias,
    __half* __restrict__ outH, float* __restrict__ outF, int mode)
{
    extern __shared__ char smem[];
    uint32_t sb = smem_u32(smem);

    int tid = threadIdx.x;
    int warp = tid >> 5, lane = tid & 31;
    int wm = warp & 3, wn = warp >> 2;
    int m0 = blockIdx.y * 128;
    int n0 = blockIdx.x * 64;

    const __half* Bhr = Bh + (size_t)n0 * Kcat;
    const __half* Blr = Bl + (size_t)n0 * Kcat;

    float acc[2][4][4];
#pragma unroll
    for (int i = 0; i < 2; i++)
#pragma unroll
        for (int j = 0; j < 4; j++)
#pragma unroll
            for (int q = 0; q < 4; q++) acc[i][j][q] = 0.f;

    int lrowA = tid >> 3;
    int ljA   = tid & 7;
    int a_row = (lane & 15);
    int a_cb  = (lane >> 4) << 4;
    int b_row = (lane & 7) + ((lane >> 4) << 3);
    int b_cb  = ((lane >> 3) & 1) << 4;

    int nch = Kcat >> 6;

    // load stage 0
    {
        uint32_t base = sb;
#pragma unroll
        for (int i = 0; i < 4; i++) {
            int row = i * 32 + lrowA;
            int gm  = m0 + row; if (gm > Nn - 1) gm = Nn - 1;
            cpa16(base + OFF_A + SWZ((uint32_t)(row * 128 + ljA * 16)),
                  A + (size_t)gm * Kcat + ljA * 8);
        }
#pragma unroll
        for (int i = 0; i < 2; i++) {
            int row = i * 32 + lrowA;
            uint32_t o = SWZ((uint32_t)(row * 128 + ljA * 16));
            cpa16(base + OFF_BH + o, Bhr + (size_t)row * Kcat + ljA * 8);
            cpa16(base + OFF_BL + o, Blr + (size_t)row * Kcat + ljA * 8);
        }
        CP_COMMIT();
    }

    for (int c = 0; c < nch; c++) {
        int buf = c & 1;
        if (c + 1 < nch) {
            uint32_t base = sb + (buf ^ 1) * STAGE;
            int acol = (c + 1) << 6;
#pragma unroll
            for (int i = 0; i < 4; i++) {
                int row = i * 32 + lrowA;
                int gm  = m0 + row; if (gm > Nn - 1) gm = Nn - 1;
                cpa16(base + OFF_A + SWZ((uint32_t)(row * 128 + ljA * 16)),
                      A + (size_t)gm * Kcat + acol + ljA * 8);
            }
#pragma unroll
            for (int i = 0; i < 2; i++) {
                int row = i * 32 + lrowA;
                uint32_t o = SWZ((uint32_t)(row * 128 + ljA * 16));
                cpa16(base + OFF_BH + o, Bhr + (size_t)row * Kcat + acol + ljA * 8);
                cpa16(base + OFF_BL + o, Blr + (size_t)row * Kcat + acol + ljA * 8);
            }
            CP_COMMIT();
            asm volatile("cp.async.wait_group 1;" ::: "memory");
        } else {
            asm volatile("cp.async.wait_group 0;" ::: "memory");
        }
        __syncthreads();

        uint32_t uA  = sb + buf * STAGE + OFF_A;
        uint32_t uBH = sb + buf * STAGE + OFF_BH;
        uint32_t uBL = sb + buf * STAGE + OFF_BL;
#pragma unroll
        for (int ks = 0; ks < 4; ks++) {
            uint32_t ah[2][4], bh[4][2], bl[4][2];
#pragma unroll
            for (int mt = 0; mt < 2; mt++) {
                uint32_t off = SWZ((uint32_t)((wm * 32 + mt * 16 + a_row) * 128 + ks * 32 + a_cb));
                ldmx4(ah[mt], uA + off);
            }
#pragma unroll
            for (int np = 0; np < 2; np++) {
                uint32_t off = SWZ((uint32_t)((wn * 32 + np * 16 + b_row) * 128 + ks * 32 + b_cb));
                uint32_t th[4], tl[4];
                ldmx4(th, uBH + off);
                ldmx4(tl, uBL + off);
                bh[np * 2][0] = th[0]; bh[np * 2][1] = th[1];
                bh[np * 2 + 1][0] = th[2]; bh[np * 2 + 1][1] = th[3];
                bl[np * 2][0] = tl[0]; bl[np * 2][1] = tl[1];
                bl[np * 2 + 1][0] = tl[2]; bl[np * 2 + 1][1] = tl[3];
            }
#pragma unroll
            for (int mt = 0; mt < 2; mt++)
#pragma unroll
                for (int nt = 0; nt < 4; nt++) {
                    mma16816(acc[mt][nt], ah[mt], bh[nt]);
                    mma16816(acc[mt][nt], ah[mt], bl[nt]);
                }
        }
        __syncthreads();
    }

    // fused epilogue: +bias, (relu), fp16 or fp32 out
    int erow = lane >> 2, ecol = (lane & 3) * 2;
#pragma unroll
    for (int mt = 0; mt < 2; mt++) {
        int gm0 = m0 + wm * 32 + mt * 16 + erow;
#pragma unroll
        for (int nt = 0; nt < 4; nt++) {
            int col = n0 + wn * 32 + nt * 8 + ecol;
            float b0 = bias[col], b1 = bias[col + 1];
            float v00 = acc[mt][nt][0] + b0, v01 = acc[mt][nt][1] + b1;
            float v10 = acc[mt][nt][2] + b0, v11 = acc[mt][nt][3] + b1;
            if (mode == 0) {
                v00 = fmaxf(v00, 0.f); v01 = fmaxf(v01, 0.f);
                v10 = fmaxf(v10, 0.f); v11 = fmaxf(v11, 0.f);
                if (gm0 < Nn)
                    *(__half2*)(outH + (size_t)gm0 * dout + col) = __floats2half2_rn(v00, v01);
                if (gm0 + 8 < Nn)
                    *(__half2*)(outH + (size_t)(gm0 + 8) * dout + col) = __floats2half2_rn(v10, v11);
            } else {
                if (gm0 < Nn)
                    *(float2*)(outF + (size_t)gm0 * dout + col) = make_float2(v00, v01);
                if (gm0 + 8 < Nn)
                    *(float2*)(outF + (size_t)(gm0 + 8) * dout + col) = make_float2(v10, v11);
            }
        }
    }
}

// ---------------- decoder ----------------
__global__ void k_wp(const float* __restrict__ Wp1, const float* __restrict__ bp1,
                     const float* __restrict__ Wp2, const float* __restrict__ bp2)
{
    int idx = blockIdx.x * blockDim.x + threadIdx.x;
    if (idx >= 513 * 8) return;
    int i = idx >> 3, c = idx & 7;
    if (i < 512) {
        float s = 0.f;
        for (int j = 0; j < 256; j++) s = fmaf(Wp1[i * 256 + j], Wp2[j * 8 + c], s);
        g_Wp[i * 8 + c] = s;
    } else {
        float s = bp2[c];
        for (int j = 0; j < 256; j++) s = fmaf(bp1[j], Wp2[j * 8 + c], s);
        g_cvec[c] = s;
    }
}

__global__ void k_q() {
    __shared__ float sWp[512 * 8];
    for (int i = threadIdx.x; i < 512 * 8; i += blockDim.x) sWp[i] = g_Wp[i];
    __syncthreads();
    int n = blockIdx.x * blockDim.x + threadIdx.x;
    if (n >= Nn) return;
    float qt[8], qb[8];
#pragma unroll
    for (int c = 0; c < 8; c++) { qt[c] = 0.f; qb[c] = 0.f; }
    const float* h2 = &g_h2[(size_t)n * 128];
    const float* h3 = &g_h3[(size_t)n * 128];
    for (int j = 0; j < 128; j++) {
        float x2 = h2[j], x3 = h3[j];
#pragma unroll
        for (int c = 0; c < 8; c++) {
            qt[c] = fmaf(x2, sWp[j * 8 + c],         qt[c]);
            qt[c] = fmaf(x3, sWp[(128 + j) * 8 + c], qt[c]);
            qb[c] = fmaf(x2, sWp[(256 + j) * 8 + c], qb[c]);
            qb[c] = fmaf(x3, sWp[(384 + j) * 8 + c], qb[c]);
        }
    }
#pragma unroll
    for (int c = 0; c < 8; c++) {
        g_Qt[(size_t)n * 8 + c] = qt[c];
        g_Qb[(size_t)n * 8 + c] = qb[c];
    }
}

__global__ void k_edge(const int* __restrict__ ds, const int* __restrict__ dd,
                       float* __restrict__ out)
{
    int e = blockIdx.x * blockDim.x + threadIdx.x;
    if (e >= EDd) return;
    int s = ds[e], d = dd[e];
    const float4* qt = (const float4*)&g_Qt[(size_t)s * 8];
    const float4* qb = (const float4*)&g_Qb[(size_t)d * 8];
    const float4* cv = (const float4*)g_cvec;
    float4 t0 = qt[0], t1 = qt[1], b0 = qb[0], b1 = qb[1], c0 = cv[0], c1 = cv[1];
    float4 o0 = make_float4(t0.x + b0.x + c0.x, t0.y + b0.y + c0.y,
                            t0.z + b0.z + c0.z, t0.w + b0.w + c0.w);
    float4 o1 = make_float4(t1.x + b1.x + c1.x, t1.y + b1.y + c1.y,
                            t1.z + b1.z + c1.z, t1.w + b1.w + c1.w);
    float4* o = (float4*)out;
    o[2 * e]     = o0;
    o[2 * e + 1] = o1;
}

// ---------------- launcher ----------------
extern "C" void kernel_launch(void* const* d_in, const int* in_sizes, int n_in,
                              void* d_out, int out_size)
{
    const float* x2  = (const float*)d_in[0];
    const float* x3  = (const float*)d_in[1];
    const int*   src = (const int*)d_in[2];
    const int*   dst = (const int*)d_in[3];
    const int*   dsr = (const int*)d_in[4];
    const int*   dds = (const int*)d_in[5];
    const float* W2a = (const float*)d_in[6];
    const float* b2a = (const float*)d_in[7];
    const float* W2b = (const float*)d_in[8];
    const float* b2b = (const float*)d_in[9];
    const float* W3a = (const float*)d_in[10];
    const float* b3a = (const float*)d_in[11];
    const float* W3b = (const float*)d_in[12];
    const float* b3b = (const float*)d_in[13];
    const float* Wp1 = (const float*)d_in[14];
    const float* bp1 = (const float*)d_in[15];
    const float* Wp2 = (const float*)d_in[16];
    const float* bp2 = (const float*)d_in[17];
    float* out = (float*)d_out;

    const int SMEM_MMA = 2 * STAGE;  // 65536
    cudaFuncSetAttribute(k_gemm, cudaFuncAttributeMaxDynamicSharedMemorySize, SMEM_MMA);

    void *pM, *pX, *pH, *pWh, *pWl, *ph2, *ph3, *pBsum;
    cudaGetSymbolAddress(&pM, g_M16);
    cudaGetSymbolAddress(&pX, g_X16);
    cudaGetSymbolAddress(&pH, g_H16);
    cudaGetSymbolAddress(&pWh, g_Wh);
    cudaGetSymbolAddress(&pWl, g_Wl);
    cudaGetSymbolAddress(&ph2, g_h2);
    cudaGetSymbolAddress(&ph3, g_h3);
    cudaGetSymbolAddress(&pBsum, g_bsum);
    __half* M  = (__half*)pM;
    __half* X  = (__half*)pX;
    __half* H  = (__half*)pH;
    __half* Wh = (__half*)pWh;
    __half* Wl = (__half*)pWl;
    float*  h2 = (float*)ph2;
    float*  h3 = (float*)ph3;
    float*  bsum = (float*)pBsum;

    // ---- graph build (CSR keyed by dst*8+rel, shared by all 4 aggregations) ----
    k_zero <<<(NK + 255) / 256, 256>>>();
    k_count<<<(TOT + 255) / 256, 256>>>(src, dst);
    k_scan1<<<(NK + 1023) / 1024, 256>>>();
    k_scan2<<<1, 32>>>((NK + 1023) / 1024);
    k_scan3<<<(NK + 255) / 256, 256>>>();
    k_fill <<<(TOT + 255) / 256, 256>>>(src, dst);
    k_bsum <<<3, 256>>>(b2a, b2b, b3a, b3b);

    dim3 gemmA(4, (Nn + 127) / 128);   // dout=256, BN=64
    dim3 gemmB(2, (Nn + 127) / 128);   // dout=128

    // ---- tower 2 (K=256, Kcat=2048) ----
    k_split_x16<<<((long long)Nn * 256 + 255) / 256, 256>>>(x2, 256, 256, X, Nn);
    k_split_w16<<<(Rr * 256 * 256 + 255) / 256, 256>>>(W2a, 256, 256, 256, Wh, Wl);
    k_aggX<<<NK, 256>>>(X, 256, M);
    k_gemm<<<gemmA, 256, SMEM_MMA>>>(M, 2048, Wh, Wl, 256, bsum + 0, H, (float*)0, 0);
    k_split_w16<<<(Rr * 128 * 256 + 255) / 256, 256>>>(W2b, 256, 256, 128, Wh, Wl);
    k_aggX<<<NK, 256>>>(H, 256, M);
    k_gemm<<<gemmB, 256, SMEM_MMA>>>(M, 2048, Wh, Wl, 128, bsum + 256, (__half*)0, h2, 1);

    // ---- tower 3 (K=300 -> pad 320, Kcat=2560) ----
    k_split_x16<<<((long long)Nn * 320 + 255) / 256, 256>>>(x3, 300, 320, X, Nn);
    k_split_w16<<<(Rr * 256 * 320 + 255) / 256, 256>>>(W3a, 300, 320, 256, Wh, Wl);
    k_aggX<<<NK, 320>>>(X, 320, M);
    k_gemm<<<gemmA, 256, SMEM_MMA>>>(M, 2560, Wh, Wl, 256, bsum + 384, H, (float*)0, 0);
    k_split_w16<<<(Rr * 128 * 256 + 255) / 256, 256>>>(W3b, 256, 256, 128, Wh, Wl);
    k_aggX<<<NK, 256>>>(H, 256, M);
    k_gemm<<<gemmB, 256, SMEM_MMA>>>(M, 2048, Wh, Wl, 128, bsum + 640, (__half*)0, h3, 1);

    // ---- decoder ----
    k_wp<<<(513 * 8 + 127) / 128, 128>>>(Wp1, bp1, Wp2, bp2);
    k_q<<<(Nn + 255) / 256, 256>>>();
    k_edge<<<(EDd + 255) / 256, 256>>>(dsr, dds, out);
}

// round 7
// speedup vs baseline: 2.3758x; 2.2676x over previous
#include <cuda_runtime.h>
#include <cuda_fp16.h>
#include <cstdint>
#include <math.h>

#define Nn  50000
#define Rr  8
#define Ee  200000
#define EDd 400000
#define TOT (Rr * Ee)
#define NK  (Nn * Rr)   // 400000 CSR keys (dst*8 + rel)

// ---------------- scratch (__device__ globals; no allocation) ----------------
__device__ __align__(16) __half g_M16[(size_t)Nn * 2560];  // Xagg [node][8*Kpad] fp16
__device__ __align__(16) __half g_X16[(size_t)Nn * 320];   // activations fp16
__device__ __align__(16) __half g_H16[(size_t)Nn * 256];   // hidden fp16
__device__ __align__(16) __half g_Wh [256 * 2560];         // Wcat^T hi [dout][8*Kpad]
__device__ __align__(16) __half g_Wl [256 * 2560];         // Wcat^T lo
__device__ __align__(16) float g_h2[(size_t)Nn * 128];
__device__ __align__(16) float g_h3[(size_t)Nn * 128];
__device__ __align__(16) float g_Qt[(size_t)Nn * 8];
__device__ __align__(16) float g_Qb[(size_t)Nn * 8];
__device__ int   g_deg_src[Rr * Nn];
__device__ int   g_deg_key[NK];
__device__ int   g_row_ptr[NK + 1];
__device__ int   g_cursor [NK];
__device__ int   g_epack  [TOT];   // src node id (rel implicit in segment)
__device__ float g_ew     [TOT];   // per-edge norm weight
__device__ int   g_blksum [512];
__device__ float g_bsum   [768];
__device__ float g_Wp     [512 * 8];
__device__ __align__(16) float g_cvec[8];

// ---------------- helpers ----------------
__device__ __forceinline__ uint32_t smem_u32(const void* p) {
    uint32_t a;
    asm("{ .reg .u64 t; cvta.to.shared.u64 t, %1; cvt.u32.u64 %0, t; }" : "=r"(a) : "l"(p));
    return a;
}
#define SWZ(b) ((b) ^ (((b) >> 3) & 0x70))

__device__ __forceinline__ void ldmx4(uint32_t* r, uint32_t addr) {
    asm volatile("ldmatrix.sync.aligned.m8n8.x4.shared.b16 {%0,%1,%2,%3}, [%4];"
        : "=r"(r[0]), "=r"(r[1]), "=r"(r[2]), "=r"(r[3]) : "r"(addr));
}
__device__ __forceinline__ void mma16816(float* c, const uint32_t* a, const uint32_t* b) {
    asm volatile(
        "mma.sync.aligned.m16n8k16.row.col.f32.f16.f16.f32 "
        "{%0,%1,%2,%3}, {%4,%5,%6,%7}, {%8,%9}, {%0,%1,%2,%3};"
        : "+f"(c[0]), "+f"(c[1]), "+f"(c[2]), "+f"(c[3])
        : "r"(a[0]), "r"(a[1]), "r"(a[2]), "r"(a[3]), "r"(b[0]), "r"(b[1]));
}
__device__ __forceinline__ void cpa16(uint32_t d, const void* s) {
    asm volatile("cp.async.cg.shared.global [%0], [%1], 16;" :: "r"(d), "l"(s));
}
#define CP_COMMIT() asm volatile("cp.async.commit_group;" ::: "memory")

// ---------------- graph build (CSR keyed by dst*8 + rel) ----------------
__global__ void k_zero() {
    int i = blockIdx.x * blockDim.x + threadIdx.x;
    if (i < NK) { g_deg_src[i] = 0; g_deg_key[i] = 0; }
}
__global__ void k_count(const int* __restrict__ src, const int* __restrict__ dst) {
    int i = blockIdx.x * blockDim.x + threadIdx.x;
    if (i < TOT) {
        int r = i / Ee;
        atomicAdd(&g_deg_src[r * Nn + src[i]], 1);
        atomicAdd(&g_deg_key[dst[i] * 8 + r], 1);
    }
}
__global__ void k_scan1() {
    __shared__ int sh[256];
    int b = blockIdx.x, t = threadIdx.x;
    int base = b * 1024 + t * 4;
    int v[4];
#pragma unroll
    for (int j = 0; j < 4; j++) {
        int idx = base + j;
        v[j] = (idx < NK) ? g_deg_key[idx] : 0;
    }
    int tsum = v[0] + v[1] + v[2] + v[3];
    sh[t] = tsum;
    __syncthreads();
    for (int off = 1; off < 256; off <<= 1) {
        int x = (t >= off) ? sh[t - off] : 0;
        __syncthreads();
        sh[t] += x;
        __syncthreads();
    }
    int run = sh[t] - tsum;
#pragma unroll
    for (int j = 0; j < 4; j++) {
        int idx = base + j;
        if (idx < NK) g_row_ptr[idx] = run;
        run += v[j];
    }
    if (t == 255) g_blksum[b] = sh[255];
}
__global__ void k_scan2(int nb) {
    if (threadIdx.x == 0 && blockIdx.x == 0) {
        int acc = 0;
        for (int i = 0; i < nb; i++) { int s = g_blksum[i]; g_blksum[i] = acc; acc += s; }
    }
}
__global__ void k_scan3() {
    int i = blockIdx.x * blockDim.x + threadIdx.x;
    if (i < NK) {
        int v = g_row_ptr[i] + g_blksum[i / 1024];
        g_row_ptr[i] = v;
        g_cursor[i]  = v;
    }
    if (i == 0) g_row_ptr[NK] = TOT;
}
__global__ void k_fill(const int* __restrict__ src, const int* __restrict__ dst) {
    int i = blockIdx.x * blockDim.x + threadIdx.x;
    if (i < TOT) {
        int r = i / Ee;
        int s = src[i], d = dst[i];
        int key = d * 8 + r;
        int pos = atomicAdd(&g_cursor[key], 1);
        g_epack[pos] = s;
        g_ew[pos] = rsqrtf((float)g_deg_src[r * Nn + s]) *
                    rsqrtf((float)g_deg_key[key]);
    }
}
__global__ void k_bsum(const float* __restrict__ b2a, const float* __restrict__ b2b,
                       const float* __restrict__ b3a, const float* __restrict__ b3b) {
    int t = blockIdx.x * blockDim.x + threadIdx.x;
    if (t < 256)      { float s = 0; for (int r = 0; r < Rr; r++) s += b2a[r * 256 + t];        g_bsum[t] = s; }
    else if (t < 384) { int j = t - 256; float s = 0; for (int r = 0; r < Rr; r++) s += b2b[r * 128 + j]; g_bsum[t] = s; }
    else if (t < 640) { int j = t - 384; float s = 0; for (int r = 0; r < Rr; r++) s += b3a[r * 256 + j]; g_bsum[t] = s; }
    else if (t < 768) { int j = t - 640; float s = 0; for (int r = 0; r < Rr; r++) s += b3b[r * 128 + j]; g_bsum[t] = s; }
}

// ---------------- fp16 conversions ----------------
__global__ void k_split_x16(const float* __restrict__ X, int K, int Kpad,
                            __half* __restrict__ out, int n)
{
    long long i = (long long)blockIdx.x * blockDim.x + threadIdx.x;
    if (i >= (long long)n * Kpad) return;
    int row = (int)(i / Kpad), k = (int)(i % Kpad);
    float v = (k < K) ? X[(size_t)row * K + k] : 0.f;
    out[i] = __float2half(v);
}

// W [r][K][dout] fp32 -> Wcat^T hi/lo [dout][8*Kpad]: entry n*(8*Kpad) + r*Kpad + k
__global__ void k_split_w16(const float* __restrict__ W, int K, int Kpad, int dout,
                            __half* __restrict__ hi, __half* __restrict__ lo)
{
    int i = blockIdx.x * blockDim.x + threadIdx.x;
    if (i >= Rr * dout * Kpad) return;
    int k = i % Kpad;
    int n = (i / Kpad) % dout;
    int r = i / (Kpad * dout);
    float v = (k < K) ? W[((size_t)r * K + k) * dout + n] : 0.f;
    __half h = __float2half(v);
    size_t d = (size_t)n * (8 * Kpad) + r * Kpad + k;
    hi[d] = h;
    lo[d] = __float2half(v - __half2float(h));
}

// ---------------- aggregation: block = dst node, warp = relation, half2 lanes ----------------
// Xagg[node*8+rel][0:Kpad] = sum_e w_e * X[src_e][0:Kpad]
// MLP = NCH2 (4 or 5) 128B loads in flight per warp per edge; X is L2-resident.
template<int NCH2>
__global__ void __launch_bounds__(256) k_aggW(const __half* __restrict__ X,
                                              __half* __restrict__ out)
{
    const int Kpad = NCH2 * 64;
    int node = blockIdx.x;
    int w = threadIdx.x >> 5, lane = threadIdx.x & 31;
    int key = node * 8 + w;
    int p0 = g_row_ptr[key], p1 = g_row_ptr[key + 1];

    float2 acc[NCH2];
#pragma unroll
    for (int c = 0; c < NCH2; c++) acc[c] = make_float2(0.f, 0.f);

    for (int p = p0; p < p1; p++) {
        int   s  = g_epack[p];
        float wt = g_ew[p];
        const __half2* xr = (const __half2*)(X + (size_t)s * Kpad) + lane;
#pragma unroll
        for (int c = 0; c < NCH2; c++) {
            float2 v = __half22float2(__ldg(&xr[c * 32]));
            acc[c].x = fmaf(wt, v.x, acc[c].x);
            acc[c].y = fmaf(wt, v.y, acc[c].y);
        }
    }

    __half2* o = (__half2*)(out + (size_t)key * Kpad) + lane;
#pragma unroll
    for (int c = 0; c < NCH2; c++)
        o[c * 32] = __floats2half2_rn(acc[c].x, acc[c].y);
}

// ---------------- pipelined HMMA fp16 2-term GEMM with fused epilogue ----------------
// C[m, n] = Xagg[m, 0:Kcat] . (Wh[n,:] + Wl[n,:]) + bias[n]  (mode0: relu->fp16, mode1: fp32)
// BM=128, BN=64, BK=64. 256 threads = 8 warps (4M x 2N), warp tile 32x32.
// cp.async double-buffered (2 stages x 32KB).
#define OFF_A  0
#define OFF_BH 16384
#define OFF_BL 24576
#define STAGE  32768

__global__ void __launch_bounds__(256, 2) k_gemm(
    const __half* __restrict__ A, int Kcat,
    const __half* __restrict__ Bh, const __half* __restrict__ Bl, int dout,
    const float* __restrict__ bias,
    __half* __restrict__ outH, float* __restrict__ outF, int mode)
{
    extern __shared__ char smem[];
    uint32_t sb = smem_u32(smem);

    int tid = threadIdx.x;
    int warp = tid >> 5, lane = tid & 31;
    int wm = warp & 3, wn = warp >> 2;
    int m0 = blockIdx.y * 128;
    int n0 = blockIdx.x * 64;

    const __half* Bhr = Bh + (size_t)n0 * Kcat;
    const __half* Blr = Bl + (size_t)n0 * Kcat;

    float acc[2][4][4];
#pragma unroll
    for (int i = 0; i < 2; i++)
#pragma unroll
        for (int j = 0; j < 4; j++)
#pragma unroll
            for (int q = 0; q < 4; q++) acc[i][j][q] = 0.f;

    int lrowA = tid >> 3;
    int ljA   = tid & 7;
    int a_row = (lane & 15);
    int a_cb  = (lane >> 4) << 4;
    int b_row = (lane & 7) + ((lane >> 4) << 3);
    int b_cb  = ((lane >> 3) & 1) << 4;

    int nch = Kcat >> 6;

    // load stage 0
    {
        uint32_t base = sb;
#pragma unroll
        for (int i = 0; i < 4; i++) {
            int row = i * 32 + lrowA;
            int gm  = m0 + row; if (gm > Nn - 1) gm = Nn - 1;
            cpa16(base + OFF_A + SWZ((uint32_t)(row * 128 + ljA * 16)),
                  A + (size_t)gm * Kcat + ljA * 8);
        }
#pragma unroll
        for (int i = 0; i < 2; i++) {
            int row = i * 32 + lrowA;
            uint32_t o = SWZ((uint32_t)(row * 128 + ljA * 16));
            cpa16(base + OFF_BH + o, Bhr + (size_t)row * Kcat + ljA * 8);
            cpa16(base + OFF_BL + o, Blr + (size_t)row * Kcat + ljA * 8);
        }
        CP_COMMIT();
    }

    for (int c = 0; c < nch; c++) {
        int buf = c & 1;
        if (c + 1 < nch) {
            uint32_t base = sb + (buf ^ 1) * STAGE;
            int acol = (c + 1) << 6;
#pragma unroll
            for (int i = 0; i < 4; i++) {
                int row = i * 32 + lrowA;
                int gm  = m0 + row; if (gm > Nn - 1) gm = Nn - 1;
                cpa16(base + OFF_A + SWZ((uint32_t)(row * 128 + ljA * 16)),
                      A + (size_t)gm * Kcat + acol + ljA * 8);
            }
#pragma unroll
            for (int i = 0; i < 2; i++) {
                int row = i * 32 + lrowA;
                uint32_t o = SWZ((uint32_t)(row * 128 + ljA * 16));
                cpa16(base + OFF_BH + o, Bhr + (size_t)row * Kcat + acol + ljA * 8);
                cpa16(base + OFF_BL + o, Blr + (size_t)row * Kcat + acol + ljA * 8);
            }
            CP_COMMIT();
            asm volatile("cp.async.wait_group 1;" ::: "memory");
        } else {
            asm volatile("cp.async.wait_group 0;" ::: "memory");
        }
        __syncthreads();

        uint32_t uA  = sb + buf * STAGE + OFF_A;
        uint32_t uBH = sb + buf * STAGE + OFF_BH;
        uint32_t uBL = sb + buf * STAGE + OFF_BL;
#pragma unroll
        for (int ks = 0; ks < 4; ks++) {
            uint32_t ah[2][4], bh[4][2], bl[4][2];
#pragma unroll
            for (int mt = 0; mt < 2; mt++) {
                uint32_t off = SWZ((uint32_t)((wm * 32 + mt * 16 + a_row) * 128 + ks * 32 + a_cb));
                ldmx4(ah[mt], uA + off);
            }
#pragma unroll
            for (int np = 0; np < 2; np++) {
                uint32_t off = SWZ((uint32_t)((wn * 32 + np * 16 + b_row) * 128 + ks * 32 + b_cb));
                uint32_t th[4], tl[4];
                ldmx4(th, uBH + off);
                ldmx4(tl, uBL + off);
                bh[np * 2][0] = th[0]; bh[np * 2][1] = th[1];
                bh[np * 2 + 1][0] = th[2]; bh[np * 2 + 1][1] = th[3];
                bl[np * 2][0] = tl[0]; bl[np * 2][1] = tl[1];
                bl[np * 2 + 1][0] = tl[2]; bl[np * 2 + 1][1] = tl[3];
            }
#pragma unroll
            for (int mt = 0; mt < 2; mt++)
#pragma unroll
                for (int nt = 0; nt < 4; nt++) {
                    mma16816(acc[mt][nt], ah[mt], bh[nt]);
                    mma16816(acc[mt][nt], ah[mt], bl[nt]);
                }
        }
        __syncthreads();
    }

    // fused epilogue: +bias, (relu), fp16 or fp32 out
    int erow = lane >> 2, ecol = (lane & 3) * 2;
#pragma unroll
    for (int mt = 0; mt < 2; mt++) {
        int gm0 = m0 + wm * 32 + mt * 16 + erow;
#pragma unroll
        for (int nt = 0; nt < 4; nt++) {
            int col = n0 + wn * 32 + nt * 8 + ecol;
            float b0 = bias[col], b1 = bias[col + 1];
            float v00 = acc[mt][nt][0] + b0, v01 = acc[mt][nt][1] + b1;
            float v10 = acc[mt][nt][2] + b0, v11 = acc[mt][nt][3] + b1;
            if (mode == 0) {
                v00 = fmaxf(v00, 0.f); v01 = fmaxf(v01, 0.f);
                v10 = fmaxf(v10, 0.f); v11 = fmaxf(v11, 0.f);
                if (gm0 < Nn)
                    *(__half2*)(outH + (size_t)gm0 * dout + col) = __floats2half2_rn(v00, v01);
                if (gm0 + 8 < Nn)
                    *(__half2*)(outH + (size_t)(gm0 + 8) * dout + col) = __floats2half2_rn(v10, v11);
            } else {
                if (gm0 < Nn)
                    *(float2*)(outF + (size_t)gm0 * dout + col) = make_float2(v00, v01);
                if (gm0 + 8 < Nn)
                    *(float2*)(outF + (size_t)(gm0 + 8) * dout + col) = make_float2(v10, v11);
            }
        }
    }
}

// ---------------- decoder ----------------
__global__ void k_wp(const float* __restrict__ Wp1, const float* __restrict__ bp1,
                     const float* __restrict__ Wp2, const float* __restrict__ bp2)
{
    int idx = blockIdx.x * blockDim.x + threadIdx.x;
    if (idx >= 513 * 8) return;
    int i = idx >> 3, c = idx & 7;
    if (i < 512) {
        float s = 0.f;
        for (int j = 0; j < 256; j++) s = fmaf(Wp1[i * 256 + j], Wp2[j * 8 + c], s);
        g_Wp[i * 8 + c] = s;
    } else {
        float s = bp2[c];
        for (int j = 0; j < 256; j++) s = fmaf(bp1[j], Wp2[j * 8 + c], s);
        g_cvec[c] = s;
    }
}

__global__ void k_q() {
    __shared__ float sWp[512 * 8];
    for (int i = threadIdx.x; i < 512 * 8; i += blockDim.x) sWp[i] = g_Wp[i];
    __syncthreads();
    int n = blockIdx.x * blockDim.x + threadIdx.x;
    if (n >= Nn) return;
    float qt[8], qb[8];
#pragma unroll
    for (int c = 0; c < 8; c++) { qt[c] = 0.f; qb[c] = 0.f; }
    const float* h2 = &g_h2[(size_t)n * 128];
    const float* h3 = &g_h3[(size_t)n * 128];
    for (int j = 0; j < 128; j++) {
        float x2 = h2[j], x3 = h3[j];
#pragma unroll
        for (int c = 0; c < 8; c++) {
            qt[c] = fmaf(x2, sWp[j * 8 + c],         qt[c]);
            qt[c] = fmaf(x3, sWp[(128 + j) * 8 + c], qt[c]);
            qb[c] = fmaf(x2, sWp[(256 + j) * 8 + c], qb[c]);
            qb[c] = fmaf(x3, sWp[(384 + j) * 8 + c], qb[c]);
        }
    }
#pragma unroll
    for (int c = 0; c < 8; c++) {
        g_Qt[(size_t)n * 8 + c] = qt[c];
        g_Qb[(size_t)n * 8 + c] = qb[c];
    }
}

__global__ void k_edge(const int* __restrict__ ds, const int* __restrict__ dd,
                       float* __restrict__ out)
{
    int e = blockIdx.x * blockDim.x + threadIdx.x;
    if (e >= EDd) return;
    int s = ds[e], d = dd[e];
    const float4* qt = (const float4*)&g_Qt[(size_t)s * 8];
    const float4* qb = (const float4*)&g_Qb[(size_t)d * 8];
    const float4* cv = (const float4*)g_cvec;
    float4 t0 = qt[0], t1 = qt[1], b0 = qb[0], b1 = qb[1], c0 = cv[0], c1 = cv[1];
    float4 o0 = make_float4(t0.x + b0.x + c0.x, t0.y + b0.y + c0.y,
                            t0.z + b0.z + c0.z, t0.w + b0.w + c0.w);
    float4 o1 = make_float4(t1.x + b1.x + c1.x, t1.y + b1.y + c1.y,
                            t1.z + b1.z + c1.z, t1.w + b1.w + c1.w);
    float4* o = (float4*)out;
    o[2 * e]     = o0;
    o[2 * e + 1] = o1;
}

// ---------------- launcher ----------------
extern "C" void kernel_launch(void* const* d_in, const int* in_sizes, int n_in,
                              void* d_out, int out_size)
{
    const float* x2  = (const float*)d_in[0];
    const float* x3  = (const float*)d_in[1];
    const int*   src = (const int*)d_in[2];
    const int*   dst = (const int*)d_in[3];
    const int*   dsr = (const int*)d_in[4];
    const int*   dds = (const int*)d_in[5];
    const float* W2a = (const float*)d_in[6];
    const float* b2a = (const float*)d_in[7];
    const float* W2b = (const float*)d_in[8];
    const float* b2b = (const float*)d_in[9];
    const float* W3a = (const float*)d_in[10];
    const float* b3a = (const float*)d_in[11];
    const float* W3b = (const float*)d_in[12];
    const float* b3b = (const float*)d_in[13];
    const float* Wp1 = (const float*)d_in[14];
    const float* bp1 = (const float*)d_in[15];
    const float* Wp2 = (const float*)d_in[16];
    const float* bp2 = (const float*)d_in[17];
    float* out = (float*)d_out;

    const int SMEM_MMA = 2 * STAGE;  // 65536
    cudaFuncSetAttribute(k_gemm, cudaFuncAttributeMaxDynamicSharedMemorySize, SMEM_MMA);

    void *pM, *pX, *pH, *pWh, *pWl, *ph2, *ph3, *pBsum;
    cudaGetSymbolAddress(&pM, g_M16);
    cudaGetSymbolAddress(&pX, g_X16);
    cudaGetSymbolAddress(&pH, g_H16);
    cudaGetSymbolAddress(&pWh, g_Wh);
    cudaGetSymbolAddress(&pWl, g_Wl);
    cudaGetSymbolAddress(&ph2, g_h2);
    cudaGetSymbolAddress(&ph3, g_h3);
    cudaGetSymbolAddress(&pBsum, g_bsum);
    __half* M  = (__half*)pM;
    __half* X  = (__half*)pX;
    __half* H  = (__half*)pH;
    __half* Wh = (__half*)pWh;
    __half* Wl = (__half*)pWl;
    float*  h2 = (float*)ph2;
    float*  h3 = (float*)ph3;
    float*  bsum = (float*)pBsum;

    // ---- graph build (CSR keyed by dst*8+rel, shared by all 4 aggregations) ----
    k_zero <<<(NK + 255) / 256, 256>>>();
    k_count<<<(TOT + 255) / 256, 256>>>(src, dst);
    k_scan1<<<(NK + 1023) / 1024, 256>>>();
    k_scan2<<<1, 32>>>((NK + 1023) / 1024);
    k_scan3<<<(NK + 255) / 256, 256>>>();
    k_fill <<<(TOT + 255) / 256, 256>>>(src, dst);
    k_bsum <<<3, 256>>>(b2a, b2b, b3a, b3b);

    dim3 gemmA(4, (Nn + 127) / 128);   // dout=256, BN=64
    dim3 gemmB(2, (Nn + 127) / 128);   // dout=128

    // ---- tower 2 (K=256, Kcat=2048) ----
    k_split_x16<<<((long long)Nn * 256 + 255) / 256, 256>>>(x2, 256, 256, X, Nn);
    k_split_w16<<<(Rr * 256 * 256 + 255) / 256, 256>>>(W2a, 256, 256, 256, Wh, Wl);
    k_aggW<4><<<Nn, 256>>>(X, M);
    k_gemm<<<gemmA, 256, SMEM_MMA>>>(M, 2048, Wh, Wl, 256, bsum + 0, H, (float*)0, 0);
    k_split_w16<<<(Rr * 128 * 256 + 255) / 256, 256>>>(W2b, 256, 256, 128, Wh, Wl);
    k_aggW<4><<<Nn, 256>>>(H, M);
    k_gemm<<<gemmB, 256, SMEM_MMA>>>(M, 2048, Wh, Wl, 128, bsum + 256, (__half*)0, h2, 1);

    // ---- tower 3 (K=300 -> pad 320, Kcat=2560) ----
    k_split_x16<<<((long long)Nn * 320 + 255) / 256, 256>>>(x3, 300, 320, X, Nn);
    k_split_w16<<<(Rr * 256 * 320 + 255) / 256, 256>>>(W3a, 300, 320, 256, Wh, Wl);
    k_aggW<5><<<Nn, 256>>>(X, M);
    k_gemm<<<gemmA, 256, SMEM_MMA>>>(M, 2560, Wh, Wl, 256, bsum + 384, H, (float*)0, 0);
    k_split_w16<<<(Rr * 128 * 256 + 255) / 256, 256>>>(W3b, 256, 256, 128, Wh, Wl);
    k_aggW<4><<<Nn, 256>>>(H, M);
    k_gemm<<<gemmB, 256, SMEM_MMA>>>(M, 2048, Wh, Wl, 128, bsum + 640, (__half*)0, h3, 1);

    // ---- decoder ----
    k_wp<<<(513 * 8 + 127) / 128, 128>>>(Wp1, bp1, Wp2, bp2);
    k_q<<<(Nn + 255) / 256, 256>>>();
    k_edge<<<(EDd + 255) / 256, 256>>>(dsr, dds, out);
}